// round 1
// baseline (speedup 1.0000x reference)
#include <cuda_runtime.h>

#define N_FFT    1024
#define HOP      512
#define CUTOFF   513
#define BATCH    16
#define T_LEN    2097152
#define N_FRAMES 4095
#define TILE     16
#define THREADS  256
#define MPAD     17   // pad 16-frame tile rows to 17 floats: conflict-free smem

__device__ __forceinline__ float2 cmul(float2 a, float2 b) {
    return make_float2(a.x * b.x - a.y * b.y, a.x * b.y + a.y * b.x);
}

extern __shared__ float smem_dyn[];

__global__ void __launch_bounds__(THREADS)
stft_mag_kernel(const float* __restrict__ in, float* __restrict__ out) {
    float2* xa  = (float2*)smem_dyn;        // 1024 complex  (8 KB)
    float2* xb  = xa + N_FFT;               // 1024 complex  (8 KB)
    float2* Wt  = xb + N_FFT;               // 256 twiddles  (2 KB)
    float*  mag = (float*)(Wt + 256);       // 513*17 floats (~34.9 KB)

    const int tid  = threadIdx.x;
    const int bidx = blockIdx.y;
    const int n0   = blockIdx.x * TILE;
    const float* g = in + (size_t)bidx * T_LEN;

    // Twiddle table: Wt[j] = exp(-2*pi*i*j/1024), j in [0,256)
    {
        float sn, cs;
        sincospif(-(float)tid / 512.0f, &sn, &cs);
        Wt[tid] = make_float2(cs, sn);
    }

    // 8 complex FFTs per block: each packs two real frames (a + i*b)
    for (int u = 0; u < TILE / 2; u++) {
        const int  f0    = n0 + 2 * u;          // always < N_FRAMES (4094 max)
        const int  f1    = f0 + 1;
        const bool f1ok  = (f1 < N_FRAMES);
        const size_t base = (size_t)f0 * HOP;

        #pragma unroll
        for (int j = tid; j < N_FFT; j += THREADS) {
            float av = g[base + j];
            float bv = f1ok ? g[base + HOP + j] : 0.0f;
            xa[j] = make_float2(av, bv);
        }
        __syncthreads();

        // Radix-4 Stockham autosort, 5 stages, ping-pong xa <-> xb
        float2* X = xa;
        float2* Y = xb;
        #pragma unroll
        for (int t = 0; t < 5; t++) {
            const int s = 1 << (2 * t);
            const int p = tid >> (2 * t);
            const int q = tid & (s - 1);

            float2 a = X[tid];
            float2 b = X[tid + 256];
            float2 c = X[tid + 512];
            float2 d = X[tid + 768];

            float2 apc  = make_float2(a.x + c.x, a.y + c.y);
            float2 amc  = make_float2(a.x - c.x, a.y - c.y);
            float2 bpd  = make_float2(b.x + d.x, b.y + d.y);
            float2 jbmd = make_float2(-(b.y - d.y), b.x - d.x);  // i*(b-d)

            float2 w1 = Wt[tid & ~(s - 1)];   // == Wt[p << 2t]
            float2 w2 = cmul(w1, w1);
            float2 w3 = cmul(w1, w2);

            const int ob = q + 4 * s * p;
            Y[ob]         = make_float2(apc.x + bpd.x, apc.y + bpd.y);
            Y[ob + s]     = cmul(w1, make_float2(amc.x - jbmd.x, amc.y - jbmd.y));
            Y[ob + 2 * s] = cmul(w2, make_float2(apc.x - bpd.x, apc.y - bpd.y));
            Y[ob + 3 * s] = cmul(w3, make_float2(amc.x + jbmd.x, amc.y + jbmd.y));
            __syncthreads();
            float2* tmp = X; X = Y; Y = tmp;
        }
        // Result (natural order) is in X.

        // Unpack two real spectra via conjugate symmetry; store magnitudes.
        #pragma unroll
        for (int k = tid; k < CUTOFF; k += THREADS) {
            float2 P = X[k];
            float2 Q = X[(N_FFT - k) & (N_FFT - 1)];
            float Ar = 0.5f * (P.x + Q.x);
            float Ai = 0.5f * (P.y - Q.y);
            mag[k * MPAD + 2 * u] = sqrtf(Ar * Ar + Ai * Ai);
            if (f1ok) {
                float Br = 0.5f * (P.y + Q.y);
                float Bi = 0.5f * (Q.x - P.x);
                mag[k * MPAD + 2 * u + 1] = sqrtf(Br * Br + Bi * Bi);
            }
        }
        // No barrier needed here: the post-load barrier of the next pair
        // orders these smem ops before any reuse of xa/xb.
    }
    __syncthreads();

    // Coalesced writeout: 16 contiguous frames per spectral row.
    const int tile_n = min(TILE, N_FRAMES - n0);
    for (int idx = tid; idx < CUTOFF * TILE; idx += THREADS) {
        int c  = idx >> 4;
        int tt = idx & 15;
        if (tt < tile_n)
            out[((size_t)bidx * CUTOFF + c) * N_FRAMES + n0 + tt] = mag[c * MPAD + tt];
    }
}

extern "C" void kernel_launch(void* const* d_in, const int* in_sizes, int n_in,
                              void* d_out, int out_size) {
    const float* in  = (const float*)d_in[0];
    float*       out = (float*)d_out;

    const int smem_bytes = (N_FFT * 2 + 256) * sizeof(float2) + CUTOFF * MPAD * sizeof(float);
    cudaFuncSetAttribute(stft_mag_kernel,
                         cudaFuncAttributeMaxDynamicSharedMemorySize, smem_bytes);

    dim3 grid((N_FRAMES + TILE - 1) / TILE, BATCH);
    stft_mag_kernel<<<grid, THREADS, smem_bytes>>>(in, out);
}

// round 4
// speedup vs baseline: 1.1924x; 1.1924x over previous
#include <cuda_runtime.h>

#define N_FFT    1024
#define HOP      512
#define CUTOFF   513
#define BATCH    16
#define T_LEN    2097152
#define N_FRAMES 4095
#define TILE     16
#define THREADS  256
#define MPAD     17   // pad 16-frame tile rows to 17 floats: conflict-free mag smem

__device__ __forceinline__ float2 cmul(float2 a, float2 b) {
    return make_float2(a.x * b.x - a.y * b.y, a.x * b.y + a.y * b.x);
}

// Bank-conflict swizzles (index is in float2 units).
// mode 0: identity; mode 1: xor bits[5:4] into [1:0]; mode 2: into [3:2].
__device__ __forceinline__ int swz(int i, int mode) {
    if (mode == 1) return i ^ ((i >> 4) & 3);
    if (mode == 2) return i ^ (((i >> 4) & 3) << 2);
    return i;
}

extern __shared__ float smem_dyn[];

__global__ void __launch_bounds__(THREADS)
stft_mag_kernel(const float* __restrict__ in, float* __restrict__ out) {
    float2* xa  = (float2*)smem_dyn;        // 1024 complex  (8 KB)
    float2* xb  = xa + N_FFT;               // 1024 complex  (8 KB)
    float2* Wt  = xb + N_FFT;               // 256 twiddles  (2 KB)
    float*  mag = (float*)(Wt + 256);       // 513*17 floats (~34.9 KB)

    const int tid  = threadIdx.x;
    const int bidx = blockIdx.y;
    const int n0   = blockIdx.x * TILE;
    const float* g = in + (size_t)bidx * T_LEN;

    // Twiddle table: Wt[j] = exp(-2*pi*i*j/1024), j in [0,256)
    {
        float sn, cs;
        sincospif(-(float)tid / 512.0f, &sn, &cs);
        Wt[tid] = make_float2(cs, sn);
    }

    // 8 complex FFTs per block: each packs two real frames (a + i*b)
    for (int u = 0; u < TILE / 2; u++) {
        const int  f0    = n0 + 2 * u;
        const int  f1    = f0 + 1;
        const bool f1ok  = (f1 < N_FRAMES);
        const size_t base = (size_t)f0 * HOP;

        // Vectorized load: frame f0 = 256 float4, frame f1 overlaps at +128.
        {
            const float4* ga = (const float4*)(g + base);
            float4 a4 = ga[tid];
            float4 b4 = make_float4(0.f, 0.f, 0.f, 0.f);
            if (f1ok) b4 = ga[tid + 128];
            xa[swz(4 * tid + 0, 1)] = make_float2(a4.x, b4.x);
            xa[swz(4 * tid + 1, 1)] = make_float2(a4.y, b4.y);
            xa[swz(4 * tid + 2, 1)] = make_float2(a4.z, b4.z);
            xa[swz(4 * tid + 3, 1)] = make_float2(a4.w, b4.w);
        }
        __syncthreads();

        // Radix-4 Stockham autosort, 5 stages, ping-pong xa <-> xb.
        // Per-stage smem swizzles: producer's write mode == consumer's read mode.
        float2* X = xa;
        float2* Y = xb;
        #pragma unroll
        for (int t = 0; t < 5; t++) {
            const int s = 1 << (2 * t);
            const int p = tid >> (2 * t);
            const int q = tid & (s - 1);
            const int rmode = (t <= 1) ? 1 : (t == 2 ? 2 : 0);
            const int wmode = (t == 0) ? 1 : (t == 1 ? 2 : 0);

            float2 a = X[swz(tid,       rmode)];
            float2 b = X[swz(tid + 256, rmode)];
            float2 c = X[swz(tid + 512, rmode)];
            float2 d = X[swz(tid + 768, rmode)];

            float2 apc  = make_float2(a.x + c.x, a.y + c.y);
            float2 amc  = make_float2(a.x - c.x, a.y - c.y);
            float2 bpd  = make_float2(b.x + d.x, b.y + d.y);
            float2 jbmd = make_float2(-(b.y - d.y), b.x - d.x);  // i*(b-d)

            float2 w1 = Wt[tid & ~(s - 1)];   // == Wt[p << 2t]
            float2 w2 = cmul(w1, w1);
            float2 w3 = cmul(w1, w2);

            const int ob = q + 4 * s * p;
            Y[swz(ob,         wmode)] = make_float2(apc.x + bpd.x, apc.y + bpd.y);
            Y[swz(ob + s,     wmode)] = cmul(w1, make_float2(amc.x - jbmd.x, amc.y - jbmd.y));
            Y[swz(ob + 2 * s, wmode)] = cmul(w2, make_float2(apc.x - bpd.x, apc.y - bpd.y));
            Y[swz(ob + 3 * s, wmode)] = cmul(w3, make_float2(amc.x + jbmd.x, amc.y + jbmd.y));
            __syncthreads();
            float2* tmp = X; X = Y; Y = tmp;
        }
        // Result (natural order, identity layout) is in X (== xb after 5 swaps).

        // Unpack two real spectra via conjugate symmetry; store magnitudes.
        #pragma unroll
        for (int k = tid; k < CUTOFF; k += THREADS) {
            float2 P = X[k];
            float2 Q = X[(N_FFT - k) & (N_FFT - 1)];
            float Ar = 0.5f * (P.x + Q.x);
            float Ai = 0.5f * (P.y - Q.y);
            mag[k * MPAD + 2 * u] = sqrtf(Ar * Ar + Ai * Ai);
            if (f1ok) {
                float Br = 0.5f * (P.y + Q.y);
                float Bi = 0.5f * (Q.x - P.x);
                mag[k * MPAD + 2 * u + 1] = sqrtf(Br * Br + Bi * Bi);
            }
        }
        // No barrier needed here: the post-load barrier of the next pair
        // orders these smem ops before any reuse of xa/xb.
    }
    __syncthreads();

    // Coalesced writeout: 16 contiguous frames per spectral row.
    const int tile_n = min(TILE, N_FRAMES - n0);
    for (int idx = tid; idx < CUTOFF * TILE; idx += THREADS) {
        int c  = idx >> 4;
        int tt = idx & 15;
        if (tt < tile_n)
            out[((size_t)bidx * CUTOFF + c) * N_FRAMES + n0 + tt] = mag[c * MPAD + tt];
    }
}

extern "C" void kernel_launch(void* const* d_in, const int* in_sizes, int n_in,
                              void* d_out, int out_size) {
    const float* in  = (const float*)d_in[0];
    float*       out = (float*)d_out;

    const int smem_bytes = (N_FFT * 2 + 256) * sizeof(float2) + CUTOFF * MPAD * sizeof(float);
    cudaFuncSetAttribute(stft_mag_kernel,
                         cudaFuncAttributeMaxDynamicSharedMemorySize, smem_bytes);

    dim3 grid((N_FRAMES + TILE - 1) / TILE, BATCH);
    stft_mag_kernel<<<grid, THREADS, smem_bytes>>>(in, out);
}

// round 5
// speedup vs baseline: 1.5045x; 1.2617x over previous
#include <cuda_runtime.h>

#define N_FFT    1024
#define HOP      512
#define CUTOFF   513
#define BATCH    16
#define T_LEN    2097152
#define N_FRAMES 4095
#define TILE     8       // 8 frames = 4 pair-packed complex FFTs per block
#define THREADS  256
#define MP       9       // mag row pad (odd stride -> conflict-free)

__device__ __forceinline__ float2 cmul(float2 a, float2 b) {
    return make_float2(a.x * b.x - a.y * b.y, a.x * b.y + a.y * b.x);
}

// In-register radix-4 butterfly (DIT, W4 = -i), outputs in natural order.
__device__ __forceinline__ void dft4(float2& a, float2& b, float2& c, float2& d) {
    float2 apc  = make_float2(a.x + c.x, a.y + c.y);
    float2 amc  = make_float2(a.x - c.x, a.y - c.y);
    float2 bpd  = make_float2(b.x + d.x, b.y + d.y);
    float2 jbmd = make_float2(-(b.y - d.y), b.x - d.x);   // i*(b-d)
    a = make_float2(apc.x + bpd.x, apc.y + bpd.y);
    b = make_float2(amc.x - jbmd.x, amc.y - jbmd.y);
    c = make_float2(apc.x - bpd.x, apc.y - bpd.y);
    d = make_float2(amc.x + jbmd.x, amc.y + jbmd.y);
}

// 16-point DFT fully in registers. Input z[n]; output y[k] at slot 4*(k&3)+(k>>2).
__device__ __forceinline__ void dft16(float2 z[16]) {
    #pragma unroll
    for (int b = 0; b < 4; b++) dft4(z[b], z[4 + b], z[8 + b], z[12 + b]);
    const float C1 = 0.9238795325112867f, S1 = 0.3826834323650898f, R2 = 0.7071067811865476f;
    const float2 W1 = make_float2( C1, -S1);
    const float2 W2 = make_float2( R2, -R2);
    const float2 W3 = make_float2( S1, -C1);
    const float2 W6 = make_float2(-R2, -R2);
    const float2 W9 = make_float2(-C1,  S1);
    // slot 4c+b holds u_b[c]; multiply by W16^{b*c}
    z[5]  = cmul(z[5],  W1);
    z[9]  = cmul(z[9],  W2);
    z[13] = cmul(z[13], W3);
    z[6]  = cmul(z[6],  W2);
    z[10] = make_float2(z[10].y, -z[10].x);   // * W16^4 = -i
    z[14] = cmul(z[14], W6);
    z[7]  = cmul(z[7],  W3);
    z[11] = cmul(z[11], W6);
    z[15] = cmul(z[15], W9);
    #pragma unroll
    for (int c = 0; c < 4; c++) dft4(z[4*c], z[4*c + 1], z[4*c + 2], z[4*c + 3]);
}

// lo[i] = t^i, hi[i] = t^(4i): acc(k) = lo[k&3]*hi[k>>2], short dep chains.
__device__ __forceinline__ void make_pows(float2 t, float2 lo[4], float2 hi[4]) {
    lo[0] = make_float2(1.f, 0.f);
    lo[1] = t;
    lo[2] = cmul(t, t);
    lo[3] = cmul(lo[2], t);
    hi[0] = make_float2(1.f, 0.f);
    hi[1] = cmul(lo[2], lo[2]);
    hi[2] = cmul(hi[1], hi[1]);
    hi[3] = cmul(hi[2], hi[1]);
}

extern __shared__ __align__(16) float smem_dyn[];

__global__ void __launch_bounds__(THREADS)
stft_mag_kernel(const float* __restrict__ in, float* __restrict__ out) {
    float2* buf = (float2*)smem_dyn;              // 4 FFTs x 1024 complex = 32 KB
    float*  mag = (float*)(buf + 4 * N_FFT);      // 513*MP floats = 18.5 KB

    const int tid  = threadIdx.x;
    const int v    = tid >> 6;       // FFT slot 0..3
    const int w    = tid & 63;       // lane within FFT
    const int bidx = blockIdx.y;
    const int n0   = blockIdx.x * TILE;
    float2* fb = buf + v * N_FFT;

    const int  f0   = n0 + 2 * v;
    const bool f1ok = (f0 + 1) < N_FRAMES;
    const float* gr = in + (size_t)bidx * T_LEN + (size_t)f0 * HOP;

    float2 z[16];

    // ---- S1: 16-pt DFT over n1 (global gather, coalesced), n2 = w ----
    {
        const int n2 = w;
        #pragma unroll
        for (int n1 = 0; n1 < 16; n1++) {
            float re = gr[64 * n1 + n2];
            float im = f1ok ? gr[HOP + 64 * n1 + n2] : 0.0f;
            z[n1] = make_float2(re, im);
        }
        dft16(z);
        float sn, cs;
        sincospif(-(float)n2 * (1.0f / 512.0f), &sn, &cs);   // W1024^{n2}
        float2 lo[4], hi[4];
        make_pows(make_float2(cs, sn), lo, hi);
        #pragma unroll
        for (int k1 = 0; k1 < 16; k1++) {
            int slot = 4 * (k1 & 3) + (k1 >> 2);
            float2 val = cmul(cmul(z[slot], lo[k1 & 3]), hi[k1 >> 2]);
            fb[64 * k1 + (n2 ^ ((k1 & 3) << 2))] = val;      // L=64k1+n2, swizzled
        }
    }
    __syncthreads();

    // ---- S2: 16-pt DFT over m1; thread = (k1 = w>>2, m2 = w&3); in-place ----
    {
        const int k1 = w >> 2, m2 = w & 3, kx = k1 & 3;
        #pragma unroll
        for (int m1 = 0; m1 < 16; m1++)
            z[m1] = fb[64 * k1 + 4 * (m1 ^ kx) + m2];
        dft16(z);
        float sn, cs;
        sincospif(-(float)m2 * (1.0f / 32.0f), &sn, &cs);    // W64^{m2}
        float2 lo[4], hi[4];
        make_pows(make_float2(cs, sn), lo, hi);
        #pragma unroll
        for (int j1 = 0; j1 < 16; j1++) {
            int slot = 4 * (j1 & 3) + (j1 >> 2);
            float2 val = cmul(cmul(z[slot], lo[j1 & 3]), hi[j1 >> 2]);
            fb[64 * k1 + 4 * (j1 ^ kx) + m2] = val;
        }
    }
    __syncthreads();

    // ---- S3: twiddle-free radix-4 over m2; read-all / barrier / scatter-write ----
    {
        const int k1 = w & 15, kx = k1 & 3, j1b = w >> 4;
        #pragma unroll
        for (int r = 0; r < 4; r++) {
            int j1 = j1b + 4 * r;
            const float4* p = (const float4*)(fb + 64 * k1 + 4 * (j1 ^ kx));
            float4 h0 = p[0], h1 = p[1];
            z[4*r + 0] = make_float2(h0.x, h0.y);
            z[4*r + 1] = make_float2(h0.z, h0.w);
            z[4*r + 2] = make_float2(h1.x, h1.y);
            z[4*r + 3] = make_float2(h1.z, h1.w);
        }
        __syncthreads();   // all reads done before in-place scatter
        #pragma unroll
        for (int r = 0; r < 4; r++) {
            int j1 = j1b + 4 * r;
            dft4(z[4*r + 0], z[4*r + 1], z[4*r + 2], z[4*r + 3]);
            int pk = k1 ^ ((j1 >> 2) << 2);                  // swizzled k1 bits
            #pragma unroll
            for (int j2 = 0; j2 < 4; j2++)
                fb[pk + 16 * j1 + 256 * j2] = z[4*r + j2];   // X at natural k (swizzled)
        }
    }
    __syncthreads();

    // ---- unpack conjugate-symmetric pair + magnitudes into mag[513][MP] ----
    for (int k = tid; k < CUTOFF; k += THREADS) {
        int physk = k ^ (((k >> 6) & 3) << 2);
        int kq    = (N_FFT - k) & (N_FFT - 1);
        int physq = kq ^ (((kq >> 6) & 3) << 2);
        #pragma unroll
        for (int vv = 0; vv < 4; vv++) {
            float2 P = buf[vv * N_FFT + physk];
            float2 Q = buf[vv * N_FFT + physq];
            float Ar = 0.5f * (P.x + Q.x), Ai = 0.5f * (P.y - Q.y);
            float Br = 0.5f * (P.y + Q.y), Bi = 0.5f * (Q.x - P.x);
            mag[k * MP + 2 * vv    ] = sqrtf(Ar * Ar + Ai * Ai);
            mag[k * MP + 2 * vv + 1] = sqrtf(Br * Br + Bi * Bi);
        }
    }
    __syncthreads();

    // ---- coalesced writeout: 8 contiguous frames per spectral row ----
    const int tile_n = min(TILE, N_FRAMES - n0);
    for (int idx = tid; idx < CUTOFF * TILE; idx += THREADS) {
        int c = idx >> 3, t = idx & 7;
        if (t < tile_n)
            out[((size_t)bidx * CUTOFF + c) * N_FRAMES + n0 + t] = mag[c * MP + t];
    }
}

extern "C" void kernel_launch(void* const* d_in, const int* in_sizes, int n_in,
                              void* d_out, int out_size) {
    const float* in  = (const float*)d_in[0];
    float*       out = (float*)d_out;

    const int smem_bytes = 4 * N_FFT * sizeof(float2) + CUTOFF * MP * sizeof(float);
    cudaFuncSetAttribute(stft_mag_kernel,
                         cudaFuncAttributeMaxDynamicSharedMemorySize, smem_bytes);

    dim3 grid((N_FRAMES + TILE - 1) / TILE, BATCH);
    stft_mag_kernel<<<grid, THREADS, smem_bytes>>>(in, out);
}

// round 6
// speedup vs baseline: 1.5491x; 1.0296x over previous
#include <cuda_runtime.h>

#define N_FFT    1024
#define HOP      512
#define CUTOFF   513
#define BATCH    16
#define T_LEN    2097152
#define N_FRAMES 4095
#define TILE     8       // 8 frames = 4 pair-packed complex FFTs per block
#define THREADS  256
#define MP       9       // mag row pad (odd stride -> conflict-free)

__device__ __forceinline__ float2 cmul(float2 a, float2 b) {
    return make_float2(a.x * b.x - a.y * b.y, a.x * b.y + a.y * b.x);
}

// In-register radix-4 butterfly (DIT, W4 = -i), outputs in natural order.
__device__ __forceinline__ void dft4(float2& a, float2& b, float2& c, float2& d) {
    float2 apc  = make_float2(a.x + c.x, a.y + c.y);
    float2 amc  = make_float2(a.x - c.x, a.y - c.y);
    float2 bpd  = make_float2(b.x + d.x, b.y + d.y);
    float2 jbmd = make_float2(-(b.y - d.y), b.x - d.x);   // i*(b-d)
    a = make_float2(apc.x + bpd.x, apc.y + bpd.y);
    b = make_float2(amc.x - jbmd.x, amc.y - jbmd.y);
    c = make_float2(apc.x - bpd.x, apc.y - bpd.y);
    d = make_float2(amc.x + jbmd.x, amc.y + jbmd.y);
}

// 16-point DFT fully in registers. Input z[n]; output y[k] at slot 4*(k&3)+(k>>2).
__device__ __forceinline__ void dft16(float2 z[16]) {
    #pragma unroll
    for (int b = 0; b < 4; b++) dft4(z[b], z[4 + b], z[8 + b], z[12 + b]);
    const float C1 = 0.9238795325112867f, S1 = 0.3826834323650898f, R2 = 0.7071067811865476f;
    const float2 W1 = make_float2( C1, -S1);
    const float2 W2 = make_float2( R2, -R2);
    const float2 W3 = make_float2( S1, -C1);
    const float2 W6 = make_float2(-R2, -R2);
    const float2 W9 = make_float2(-C1,  S1);
    z[5]  = cmul(z[5],  W1);
    z[9]  = cmul(z[9],  W2);
    z[13] = cmul(z[13], W3);
    z[6]  = cmul(z[6],  W2);
    z[10] = make_float2(z[10].y, -z[10].x);   // * W16^4 = -i
    z[14] = cmul(z[14], W6);
    z[7]  = cmul(z[7],  W3);
    z[11] = cmul(z[11], W6);
    z[15] = cmul(z[15], W9);
    #pragma unroll
    for (int c = 0; c < 4; c++) dft4(z[4*c], z[4*c + 1], z[4*c + 2], z[4*c + 3]);
}

// lo[i] = t^i, hi[i] = t^(4i): acc(k) = lo[k&3]*hi[k>>2], short dep chains.
__device__ __forceinline__ void make_pows(float2 t, float2 lo[4], float2 hi[4]) {
    lo[0] = make_float2(1.f, 0.f);
    lo[1] = t;
    lo[2] = cmul(t, t);
    lo[3] = cmul(lo[2], t);
    hi[0] = make_float2(1.f, 0.f);
    hi[1] = cmul(lo[2], lo[2]);
    hi[2] = cmul(hi[1], hi[1]);
    hi[3] = cmul(hi[2], hi[1]);
}

// Read quad (K,J): 4 complex m2-values, stored with m2-swizzle s=(J>>2)&3.
__device__ __forceinline__ void load_quad(const float2* __restrict__ fb, int K, int J, float2 q[4]) {
    const int base = 64 * K + 4 * (J ^ (K & 3));
    const int s = (J >> 2) & 3;
    #pragma unroll
    for (int m = 0; m < 4; m++) q[m] = fb[base + (m ^ s)];
}

// P,Q conjugate pair of the pair-packed FFT -> two frame magnitudes at bin k.
// Magnitudes are invariant under P<->Q swap (Ai, Bi flip sign only).
__device__ __forceinline__ void pair_mags(float* mag, int k, int v2, float2 P, float2 Q) {
    float Ar = 0.5f * (P.x + Q.x), Ai = 0.5f * (P.y - Q.y);
    float Br = 0.5f * (P.y + Q.y), Bi = 0.5f * (Q.x - P.x);
    mag[k * MP + v2    ] = sqrtf(Ar * Ar + Ai * Ai);
    mag[k * MP + v2 + 1] = sqrtf(Br * Br + Bi * Bi);
}

// One orbit: quad A=(k1,j1) and its conjugate quad B. Emits 4 bins.
__device__ __forceinline__ void orbit_mags(const float2* __restrict__ fb, float* mag, int v2,
                                           int k1, int j1, int k1B, int j1B) {
    float2 A[4], B[4];
    load_quad(fb, k1,  j1,  A);
    load_quad(fb, k1B, j1B, B);
    dft4(A[0], A[1], A[2], A[3]);   // A[j2] = X[k1+16*j1+256*j2]
    dft4(B[0], B[1], B[2], B[3]);
    const int kb = k1 + 16 * j1;
    #pragma unroll
    for (int j2 = 0; j2 < 4; j2++) {
        int kd = kb + 256 * j2;
        int k  = (j2 < 2) ? kd : (1024 - kd);   // pick the member < 513
        pair_mags(mag, k, v2, A[j2], B[3 - j2]);
    }
}

extern __shared__ __align__(16) float smem_dyn[];

__global__ void __launch_bounds__(THREADS)
stft_mag_kernel(const float* __restrict__ in, float* __restrict__ out) {
    float2* buf = (float2*)smem_dyn;              // 4 FFTs x 1024 complex = 32 KB
    float*  mag = (float*)(buf + 4 * N_FFT);      // 513*MP floats = 18.5 KB

    const int tid  = threadIdx.x;
    const int v    = tid >> 6;       // FFT slot 0..3
    const int w    = tid & 63;       // lane within FFT
    const int v2   = 2 * v;
    const int bidx = blockIdx.y;
    const int n0   = blockIdx.x * TILE;
    float2* fb = buf + v * N_FFT;

    const int  f0   = n0 + 2 * v;
    const bool f1ok = (f0 + 1) < N_FRAMES;
    const float* gr = in + (size_t)bidx * T_LEN + (size_t)f0 * HOP;

    float2 z[16];

    // ---- S1: 16-pt DFT over n1 (global gather, coalesced), n2 = w ----
    {
        const int n2 = w;
        #pragma unroll
        for (int n1 = 0; n1 < 16; n1++) {
            float re = gr[64 * n1 + n2];
            float im = f1ok ? gr[HOP + 64 * n1 + n2] : 0.0f;
            z[n1] = make_float2(re, im);
        }
        dft16(z);
        float sn, cs;
        sincospif(-(float)n2 * (1.0f / 512.0f), &sn, &cs);   // W1024^{n2}
        float2 lo[4], hi[4];
        make_pows(make_float2(cs, sn), lo, hi);
        #pragma unroll
        for (int k1 = 0; k1 < 16; k1++) {
            int slot = 4 * (k1 & 3) + (k1 >> 2);
            float2 val = cmul(cmul(z[slot], lo[k1 & 3]), hi[k1 >> 2]);
            fb[64 * k1 + (n2 ^ ((k1 & 3) << 2))] = val;      // n2 bits[2:3] swizzle
        }
    }
    __syncthreads();

    // ---- S2: 16-pt DFT over m1; thread = (k1 = w>>2, m2 = w&3) ----
    {
        const int k1 = w >> 2, m2 = w & 3, kx = k1 & 3;
        #pragma unroll
        for (int m1 = 0; m1 < 16; m1++)
            z[m1] = fb[64 * k1 + 4 * (m1 ^ kx) + m2];
        dft16(z);
        float sn, cs;
        sincospif(-(float)m2 * (1.0f / 32.0f), &sn, &cs);    // W64^{m2}
        float2 lo[4], hi[4];
        make_pows(make_float2(cs, sn), lo, hi);
        // m2-swizzled write is NOT in-place: ensure all reads done first.
        __syncthreads();
        #pragma unroll
        for (int j1 = 0; j1 < 16; j1++) {
            int slot = 4 * (j1 & 3) + (j1 >> 2);
            float2 val = cmul(cmul(z[slot], lo[j1 & 3]), hi[j1 >> 2]);
            fb[64 * k1 + 4 * (j1 ^ kx) + (m2 ^ ((j1 >> 2) & 3))] = val;
        }
    }
    __syncthreads();

    // ---- fused last radix-4 + conjugate unpack + magnitudes ----
    // 127 two-quad orbits + 2 self-paired quads cover all 513 bins exactly once.
    #pragma unroll
    for (int i = 0; i < 2; i++) {
        const int o = 2 * w + i;
        if (o < 127) {
            int k1, j1;
            if (o < 112)      { k1 = 1 + (o >> 4); j1 = o & 15;  }
            else if (o < 120) { k1 = 8;            j1 = o - 112; }
            else              { k1 = 0;            j1 = o - 119; }
            const int k1B = (16 - k1) & 15;
            const int j1B = (k1 == 0) ? (16 - j1) : (15 - j1);
            orbit_mags(fb, mag, v2, k1, j1, k1B, j1B);
        } else if (o == 127) {
            // self-paired quads (0,0) and (0,8)
            float2 A[4];
            load_quad(fb, 0, 0, A);
            dft4(A[0], A[1], A[2], A[3]);       // X[0],X[256],X[512],X[768]
            mag[0 * MP + v2]       = fabsf(A[0].x);
            mag[0 * MP + v2 + 1]   = fabsf(A[0].y);
            pair_mags(mag, 256, v2, A[1], A[3]);
            mag[512 * MP + v2]     = fabsf(A[2].x);
            mag[512 * MP + v2 + 1] = fabsf(A[2].y);
            load_quad(fb, 0, 8, A);
            dft4(A[0], A[1], A[2], A[3]);       // X[128],X[384],X[640],X[896]
            pair_mags(mag, 128, v2, A[0], A[3]);
            pair_mags(mag, 384, v2, A[1], A[2]);
        }
    }
    __syncthreads();

    // ---- coalesced writeout: 8 contiguous frames per spectral row ----
    const int tile_n = min(TILE, N_FRAMES - n0);
    for (int idx = tid; idx < CUTOFF * TILE; idx += THREADS) {
        int c = idx >> 3, t = idx & 7;
        if (t < tile_n)
            out[((size_t)bidx * CUTOFF + c) * N_FRAMES + n0 + t] = mag[c * MP + t];
    }
}

extern "C" void kernel_launch(void* const* d_in, const int* in_sizes, int n_in,
                              void* d_out, int out_size) {
    const float* in  = (const float*)d_in[0];
    float*       out = (float*)d_out;

    const int smem_bytes = 4 * N_FFT * sizeof(float2) + CUTOFF * MP * sizeof(float);
    cudaFuncSetAttribute(stft_mag_kernel,
                         cudaFuncAttributeMaxDynamicSharedMemorySize, smem_bytes);

    dim3 grid((N_FRAMES + TILE - 1) / TILE, BATCH);
    stft_mag_kernel<<<grid, THREADS, smem_bytes>>>(in, out);
}